// round 3
// baseline (speedup 1.0000x reference)
#include <cuda_runtime.h>
#include <math.h>

#define TSTEPS 128
#define NBATCH 256
#define DDIM 1024
#define HDIM 1024
#define JDIM 256
#define LRATE 1e-3f

#define NJ (NBATCH * JDIM)          // 65536
#define NH (NBATCH * HDIM)          // 262144
#define JH (JDIM * HDIM)            // 262144

// ---------------- device scratch (no allocations allowed) -------------------
__device__ float g_Z[(size_t)TSTEPS * NBATCH * HDIM];
__device__ float g_Y[(size_t)TSTEPS * NBATCH * HDIM];
__device__ float g_Q[(size_t)TSTEPS * NBATCH * HDIM];

__device__ float g_W1[JH];
__device__ float g_b1[JDIM];
__device__ float g_W2[JH];
__device__ float g_b2[HDIM];

__device__ float g_PRE[NJ];
__device__ float g_H[NJ];
__device__ float g_DOUT[NH];
__device__ float g_DPRE[NJ];

__device__ float g_P1[8 * NJ];
__device__ float g_P2[2 * NH];
__device__ float g_P3[8 * NJ];
__device__ float g_PW2[2 * JH];
__device__ float g_PW1[2 * JH];

__device__ unsigned int g_cnt = 0;
__device__ unsigned int g_gen = 0;

// ---------------- helpers ----------------------------------------------------
__device__ __forceinline__ float gelu_f(float x) {
    return 0.5f * x * (1.0f + erff(x * 0.70710678118654752f));
}
__device__ __forceinline__ float gelu_grad_f(float x) {
    float cdf = 0.5f * (1.0f + erff(x * 0.70710678118654752f));
    float pdf = 0.3989422804014327f * expf(-0.5f * x * x);
    return cdf + x * pdf;
}

__device__ __forceinline__ void grid_barrier() {
    __syncthreads();
    if (threadIdx.x == 0) {
        unsigned int gen = *((volatile unsigned int*)&g_gen);
        __threadfence();
        unsigned int t = atomicAdd(&g_cnt, 1u);
        if (t == gridDim.x - 1) {
            g_cnt = 0;
            __threadfence();
            *((volatile unsigned int*)&g_gen) = gen + 1u;
        } else {
            while (*((volatile unsigned int*)&g_gen) == gen) { }
        }
        __threadfence();
    }
    __syncthreads();
}

// ---------------- TF32 split + MMA primitives --------------------------------
__device__ __forceinline__ void split_tf32(float x, float& hi, float& lo) {
    unsigned h;
    asm("cvt.rna.tf32.f32 %0, %1;" : "=r"(h) : "f"(x));
    float hf = __uint_as_float(h);
    float lf = x - hf;
    unsigned l;
    asm("cvt.rna.tf32.f32 %0, %1;" : "=r"(l) : "f"(lf));
    hi = hf;
    lo = __uint_as_float(l);
}

__device__ __forceinline__ void mma_tf32(float c[4], const unsigned a[4], const unsigned b[2]) {
    asm volatile(
        "mma.sync.aligned.m16n8k8.row.col.f32.tf32.tf32.f32 "
        "{%0,%1,%2,%3},{%4,%5,%6,%7},{%8,%9},{%0,%1,%2,%3};\n"
        : "+f"(c[0]), "+f"(c[1]), "+f"(c[2]), "+f"(c[3])
        : "r"(a[0]), "r"(a[1]), "r"(a[2]), "r"(a[3]), "r"(b[0]), "r"(b[1]));
}

// ---------------- 64x64 tensor-core GEMM tile --------------------------------
// smem [k][mn] stride 72: fragment LDS bank = 8*tg + g -> conflict-free.
struct SmemT {
    float Ah[16][72];
    float Al[16][72];
    float Bh[16][72];
    float Bl[16][72];
};

__device__ __forceinline__ void ld_trans_sp(float hi[16][72], float lo[16][72],
                                            const float* __restrict__ src,
                                            int r0, int k0, int ld, int tid) {
    // src[row][k] (k fastest): transpose into [kk][rr]
#pragma unroll
    for (int i = 0; i < 4; i++) {
        int e = tid + 256 * i;
        int rr = e >> 4, kk = e & 15;
        float x = __ldcg(&src[(size_t)(r0 + rr) * ld + (k0 + kk)]);
        split_tf32(x, hi[kk][rr], lo[kk][rr]);
    }
}
__device__ __forceinline__ void ld_direct_sp(float hi[16][72], float lo[16][72],
                                             const float* __restrict__ src,
                                             int k0, int c0, int ld, int tid) {
    // src[k][col] (col fastest): direct copy [kk][cc]
#pragma unroll
    for (int i = 0; i < 4; i++) {
        int e = tid + 256 * i;
        int kk = e >> 6, cc = e & 63;
        float x = __ldcg(&src[(size_t)(k0 + kk) * ld + (c0 + cc)]);
        split_tf32(x, hi[kk][cc], lo[kk][cc]);
    }
}

// MODE 0: NT  C=A@B^T   A[M][K], B[N][K]
// MODE 1: NN  C=A@B     A[M][K], B[K][N]
// MODE 2: TN  C=A^T@B   A[K][M], B[K][N]
template <int MODE>
__device__ void gemm_tile(const float* __restrict__ A, const float* __restrict__ B,
                          float* __restrict__ C, int M, int N, int K,
                          int m0, int n0, int k0, int Kc, SmemT& s) {
    const int tid = threadIdx.x;
    const int lane = tid & 31;
    const int wid = tid >> 5;
    const int wm = wid & 1;        // 2 warps in M (32 rows each)
    const int wn = wid >> 1;       // 4 warps in N (16 cols each)
    const int g = lane >> 2;       // 0..7
    const int tg = lane & 3;       // 0..3

    float acc[2][2][4];
#pragma unroll
    for (int f = 0; f < 2; f++)
#pragma unroll
        for (int j = 0; j < 2; j++)
#pragma unroll
            for (int r = 0; r < 4; r++) acc[f][j][r] = 0.0f;

    for (int kc = 0; kc < Kc; kc += 16) {
        __syncthreads();
        int kb = k0 + kc;
        if (MODE == 0) {
            ld_trans_sp(s.Ah, s.Al, A, m0, kb, K, tid);
            ld_trans_sp(s.Bh, s.Bl, B, n0, kb, K, tid);
        } else if (MODE == 1) {
            ld_trans_sp(s.Ah, s.Al, A, m0, kb, K, tid);
            ld_direct_sp(s.Bh, s.Bl, B, kb, n0, N, tid);
        } else {
            ld_direct_sp(s.Ah, s.Al, A, kb, m0, M, tid);
            ld_direct_sp(s.Bh, s.Bl, B, kb, n0, N, tid);
        }
        __syncthreads();

#pragma unroll
        for (int ks = 0; ks < 16; ks += 8) {
            unsigned ah[2][4], al[2][4], bh[2][2], bl[2][2];
#pragma unroll
            for (int f = 0; f < 2; f++) {
                int rb = wm * 32 + f * 16;
                ah[f][0] = __float_as_uint(s.Ah[ks + tg][rb + g]);
                ah[f][1] = __float_as_uint(s.Ah[ks + tg][rb + g + 8]);
                ah[f][2] = __float_as_uint(s.Ah[ks + tg + 4][rb + g]);
                ah[f][3] = __float_as_uint(s.Ah[ks + tg + 4][rb + g + 8]);
                al[f][0] = __float_as_uint(s.Al[ks + tg][rb + g]);
                al[f][1] = __float_as_uint(s.Al[ks + tg][rb + g + 8]);
                al[f][2] = __float_as_uint(s.Al[ks + tg + 4][rb + g]);
                al[f][3] = __float_as_uint(s.Al[ks + tg + 4][rb + g + 8]);
            }
#pragma unroll
            for (int j = 0; j < 2; j++) {
                int cb = wn * 16 + j * 8;
                bh[j][0] = __float_as_uint(s.Bh[ks + tg][cb + g]);
                bh[j][1] = __float_as_uint(s.Bh[ks + tg + 4][cb + g]);
                bl[j][0] = __float_as_uint(s.Bl[ks + tg][cb + g]);
                bl[j][1] = __float_as_uint(s.Bl[ks + tg + 4][cb + g]);
            }
#pragma unroll
            for (int f = 0; f < 2; f++)
#pragma unroll
                for (int j = 0; j < 2; j++) {
                    mma_tf32(acc[f][j], ah[f], bh[j]);
                    mma_tf32(acc[f][j], ah[f], bl[j]);
                    mma_tf32(acc[f][j], al[f], bh[j]);
                }
        }
    }

#pragma unroll
    for (int f = 0; f < 2; f++)
#pragma unroll
        for (int j = 0; j < 2; j++) {
            int row = m0 + wm * 32 + f * 16 + g;
            int col = n0 + wn * 16 + j * 8 + 2 * tg;
            *(float2*)&C[(size_t)row * N + col] =
                make_float2(acc[f][j][0], acc[f][j][1]);
            *(float2*)&C[(size_t)(row + 8) * N + col] =
                make_float2(acc[f][j][2], acc[f][j][3]);
        }
}

template <int MODE>
__device__ void gemm_phase(const float* __restrict__ A, const float* __restrict__ B,
                           float* __restrict__ Cpart, int M, int N, int K, int S,
                           SmemT& s) {
    const int tilesN = N >> 6;
    const int tilesM = M >> 6;
    const int units = tilesM * tilesN * S;
    const int Kc = K / S;
    for (int u = blockIdx.x; u < units; u += gridDim.x) {
        int sp = u % S;
        int tmn = u / S;
        int tn = tmn % tilesN, tm = tmn / tilesN;
        gemm_tile<MODE>(A, B, Cpart + (size_t)sp * M * N, M, N, K,
                        tm << 6, tn << 6, sp * Kc, Kc, s);
    }
}

// ---------------- kernels ----------------------------------------------------
__global__ void init_kernel(const float* __restrict__ W1, const float* __restrict__ b1,
                            const float* __restrict__ W2, const float* __restrict__ b2) {
    int i = blockIdx.x * blockDim.x + threadIdx.x;
    int nth = gridDim.x * blockDim.x;
    for (int k = i; k < JH; k += nth) g_W1[k] = W1[k];
    for (int k = i; k < JH; k += nth) g_W2[k] = W2[k];
    for (int k = i; k < JDIM; k += nth) g_b1[k] = b1[k];
    for (int k = i; k < HDIM; k += nth) g_b2[k] = b2[k];
}

__global__ void __launch_bounds__(256) proj_kernel(const float* __restrict__ X,
                                                   const float* __restrict__ Tk,
                                                   const float* __restrict__ Tv,
                                                   const float* __restrict__ Tq) {
    __shared__ SmemT sm;
    const float* W;
    float* C;
    if (blockIdx.z == 0)      { W = Tk; C = g_Z; }
    else if (blockIdx.z == 1) { W = Tv; C = g_Y; }
    else                      { W = Tq; C = g_Q; }
    gemm_tile<0>(X, W, C, TSTEPS * NBATCH, HDIM, DDIM,
                 blockIdx.y * 64, blockIdx.x * 64, 0, DDIM, sm);
}

__global__ void __launch_bounds__(256, 1) scan_kernel(float* __restrict__ out) {
    __shared__ SmemT sm;
    const int tid = threadIdx.x;
    const int gth = blockIdx.x * 256 + tid;
    const int nth = gridDim.x * 256;
    const int w = gth >> 5;
    const int lane = gth & 31;
    const float cL = 2.0f / (float)(NBATCH * HDIM);

    for (int t = 0; t < TSTEPS; t++) {
        const float* Zt = g_Z + (size_t)t * NH;
        const float* Yt = g_Y + (size_t)t * NH;
        const float* Qt = g_Q + (size_t)t * NH;

        // P1: pre parts = Zt @ W1^T   [256,256] K=1024, S=8 -> 128 units
        gemm_phase<0>(Zt, g_W1, g_P1, NBATCH, JDIM, HDIM, 8, sm);
        grid_barrier();

        // E1: pre = sum + b1; h = gelu(pre)
        for (int i = gth; i < NJ; i += nth) {
            float s = __ldcg(&g_b1[i & (JDIM - 1)]);
#pragma unroll
            for (int p = 0; p < 8; p++) s += __ldcg(&g_P1[p * NJ + i]);
            g_PRE[i] = s;
            g_H[i] = gelu_f(s);
        }
        grid_barrier();

        // P2: out2 parts = H @ W2^T   [256,1024] K=256, S=2 -> 128 units
        gemm_phase<0>(g_H, g_W2, g_P2, NBATCH, HDIM, JDIM, 2, sm);
        grid_barrier();

        // E2: dout = cL * (z + out2 + b2 - y)
        for (int i = gth; i < NH; i += nth) {
            float o = __ldcg(&g_P2[i]) + __ldcg(&g_P2[NH + i]);
            float r = __ldcg(&Zt[i]) + o + __ldcg(&g_b2[i & (HDIM - 1)]);
            g_DOUT[i] = cL * (r - __ldcg(&Yt[i]));
        }
        grid_barrier();

        // P3: dh parts = DOUT @ W2 (NN)  [256,256] K=1024, S=8
        gemm_phase<1>(g_DOUT, g_W2, g_P3, NBATCH, JDIM, HDIM, 8, sm);
        // P4: gw2 parts = DOUT^T @ H (TN) [1024,256] K=256, S=2
        gemm_phase<2>(g_DOUT, g_H, g_PW2, HDIM, JDIM, NBATCH, 2, sm);
        grid_barrier();

        // E3: dpre = (sum dh parts) * gelu'(pre)
        for (int i = gth; i < NJ; i += nth) {
            float s = 0.0f;
#pragma unroll
            for (int p = 0; p < 8; p++) s += __ldcg(&g_P3[p * NJ + i]);
            g_DPRE[i] = s * gelu_grad_f(__ldcg(&g_PRE[i]));
        }
        grid_barrier();

        // P5: gw1 parts = DPRE^T @ Zt (TN) [256,1024] K=256, S=2
        gemm_phase<2>(g_DPRE, Zt, g_PW1, JDIM, HDIM, NBATCH, 2, sm);
        grid_barrier();

        // E4: SGD update (grads read pre-update params, all partials ready)
        for (int i = gth; i < JH; i += nth) {
            float g = __ldcg(&g_PW1[i]) + __ldcg(&g_PW1[JH + i]);
            g_W1[i] = __ldcg(&g_W1[i]) - LRATE * g;
        }
        for (int i = gth; i < JH; i += nth) {
            float g = __ldcg(&g_PW2[i]) + __ldcg(&g_PW2[JH + i]);
            g_W2[i] = __ldcg(&g_W2[i]) - LRATE * g;
        }
        // bias grads: one warp per column, shuffle reduce
        if (w < JDIM) {
            float s = 0.0f;
#pragma unroll
            for (int r = 0; r < 8; r++)
                s += __ldcg(&g_DPRE[(lane + 32 * r) * JDIM + w]);
#pragma unroll
            for (int o = 16; o > 0; o >>= 1) s += __shfl_xor_sync(0xFFFFFFFFu, s, o);
            if (lane == 0) g_b1[w] = __ldcg(&g_b1[w]) - LRATE * s;
        }
        if (w < HDIM) {
            float s = 0.0f;
#pragma unroll
            for (int r = 0; r < 8; r++)
                s += __ldcg(&g_DOUT[(lane + 32 * r) * HDIM + w]);
#pragma unroll
            for (int o = 16; o > 0; o >>= 1) s += __shfl_xor_sync(0xFFFFFFFFu, s, o);
            if (lane == 0) g_b2[w] = __ldcg(&g_b2[w]) - LRATE * s;
        }
        grid_barrier();

        // P6: pre2 parts = Qt @ W1_new^T  [256,256] K=1024, S=8
        gemm_phase<0>(Qt, g_W1, g_P1, NBATCH, JDIM, HDIM, 8, sm);
        grid_barrier();

        // E5: h2 = gelu(pre2 + b1_new)
        for (int i = gth; i < NJ; i += nth) {
            float s = __ldcg(&g_b1[i & (JDIM - 1)]);
#pragma unroll
            for (int p = 0; p < 8; p++) s += __ldcg(&g_P1[p * NJ + i]);
            g_H[i] = gelu_f(s);
        }
        grid_barrier();

        // P7: out parts = H2 @ W2_new^T  [256,1024] K=256, S=2
        gemm_phase<0>(g_H, g_W2, g_P2, NBATCH, HDIM, JDIM, 2, sm);
        grid_barrier();

        // E6: out[t] = q + out2 + b2_new
        float* Ot = out + (size_t)t * NH;
        for (int i = gth; i < NH; i += nth) {
            float o = __ldcg(&g_P2[i]) + __ldcg(&g_P2[NH + i]);
            Ot[i] = __ldcg(&Qt[i]) + o + __ldcg(&g_b2[i & (HDIM - 1)]);
        }
        grid_barrier();
    }
}

// ---------------- launch -----------------------------------------------------
extern "C" void kernel_launch(void* const* d_in, const int* in_sizes, int n_in,
                              void* d_out, int out_size) {
    const float* X  = (const float*)d_in[0];
    const float* Tk = (const float*)d_in[1];
    const float* Tv = (const float*)d_in[2];
    const float* Tq = (const float*)d_in[3];
    const float* W1 = (const float*)d_in[4];
    const float* b1 = (const float*)d_in[5];
    const float* W2 = (const float*)d_in[6];
    const float* b2 = (const float*)d_in[7];
    float* out = (float*)d_out;

    init_kernel<<<256, 256>>>(W1, b1, W2, b2);
    dim3 pg(HDIM / 64, (TSTEPS * NBATCH) / 64, 3);
    proj_kernel<<<pg, 256>>>(X, Tk, Tv, Tq);
    scan_kernel<<<128, 256>>>(out);
}